// round 3
// baseline (speedup 1.0000x reference)
#include <cuda_runtime.h>
#include <math.h>

// Problem constants
#define SQ   3136          // sequence length
#define NH   16            // heads
#define HD   80            // head dim
#define HID  1280          // NH*HD
#define HID3 3840          // 3*HID
#define SCALE 0.11180339887498948f  // 1/sqrt(80)

// ---------------- scratch (device globals; no allocs allowed) ----------------
__device__ float g_qkv[(size_t)SQ * HID3];            // 48.2 MB
__device__ float g_q[(size_t)NH * SQ * HD];           // 16 MB
__device__ float g_k[(size_t)NH * SQ * HD];           // 16 MB
__device__ float g_v[(size_t)NH * SQ * HD];           // 16 MB
__device__ float g_attn[(size_t)SQ * HID];            // 16 MB

// =============================================================================
// SGEMM NT:  C[M,N] = A[M,K] @ B[N,K]^T + bias[N]  (+ optional residual[M,N])
// BM=BN=128, BK=8, 256 threads, 8x8 microtile (split 4+4 cutlass-style).
// N, K must be multiples of 128 / 8 (true here); M guarded.
// =============================================================================
template <bool RESID>
__global__ __launch_bounds__(256)
void sgemm_nt_kernel(float* __restrict__ C,
                     const float* __restrict__ A,
                     const float* __restrict__ B,
                     const float* __restrict__ bias,
                     const float* __restrict__ Rz,
                     int M, int N, int K)
{
    __shared__ float As[8][128];
    __shared__ float Bs[8][128];

    const int tid = threadIdx.x;
    const int tx = tid & 15;          // 0..15 (N direction)
    const int ty = tid >> 4;          // 0..15 (M direction)
    const int n0 = blockIdx.x * 128;
    const int m0 = blockIdx.y * 128;

    const int lr = tid >> 1;          // 0..127 row within tile
    const int lc = (tid & 1) * 4;     // 0 or 4 k-offset

    float acc[8][8];
#pragma unroll
    for (int i = 0; i < 8; i++)
#pragma unroll
        for (int j = 0; j < 8; j++) acc[i][j] = 0.f;

    for (int k0 = 0; k0 < K; k0 += 8) {
        float4 a4 = make_float4(0.f, 0.f, 0.f, 0.f);
        const int am = m0 + lr;
        if (am < M) a4 = *(const float4*)&A[(size_t)am * K + k0 + lc];
        float4 b4 = *(const float4*)&B[(size_t)(n0 + lr) * K + k0 + lc];

        __syncthreads();   // previous tile's compute done before overwrite
        As[lc + 0][lr] = a4.x;  As[lc + 1][lr] = a4.y;
        As[lc + 2][lr] = a4.z;  As[lc + 3][lr] = a4.w;
        Bs[lc + 0][lr] = b4.x;  Bs[lc + 1][lr] = b4.y;
        Bs[lc + 2][lr] = b4.z;  Bs[lc + 3][lr] = b4.w;
        __syncthreads();

#pragma unroll
        for (int kk = 0; kk < 8; kk++) {
            float4 a0 = *(const float4*)&As[kk][ty * 4];
            float4 a1 = *(const float4*)&As[kk][64 + ty * 4];
            float4 b0 = *(const float4*)&Bs[kk][tx * 4];
            float4 b1 = *(const float4*)&Bs[kk][64 + tx * 4];
            float ar[8] = {a0.x, a0.y, a0.z, a0.w, a1.x, a1.y, a1.z, a1.w};
            float br[8] = {b0.x, b0.y, b0.z, b0.w, b1.x, b1.y, b1.z, b1.w};
#pragma unroll
            for (int i = 0; i < 8; i++)
#pragma unroll
                for (int j = 0; j < 8; j++)
                    acc[i][j] += ar[i] * br[j];
        }
    }

    // epilogue
#pragma unroll
    for (int ih = 0; ih < 2; ih++) {
#pragma unroll
        for (int ii = 0; ii < 4; ii++) {
            const int m = m0 + ih * 64 + ty * 4 + ii;
            if (m >= M) continue;
            const int i = ih * 4 + ii;
#pragma unroll
            for (int jh = 0; jh < 2; jh++) {
                const int n = n0 + jh * 64 + tx * 4;
                float4 bv = *(const float4*)&bias[n];
                float4 o;
                o.x = acc[i][jh * 4 + 0] + bv.x;
                o.y = acc[i][jh * 4 + 1] + bv.y;
                o.z = acc[i][jh * 4 + 2] + bv.z;
                o.w = acc[i][jh * 4 + 3] + bv.w;
                if (RESID) {
                    float4 rv = *(const float4*)&Rz[(size_t)m * N + n];
                    o.x += rv.x; o.y += rv.y; o.z += rv.z; o.w += rv.w;
                }
                *(float4*)&C[(size_t)m * N + n] = o;
            }
        }
    }
}

// =============================================================================
// RoPE + split qkv -> q/k/v in [H, S, D] layout
// =============================================================================
__global__ void rope_split_kernel(const float* __restrict__ cosb,
                                  const float* __restrict__ sinb)
{
    const int s = blockIdx.x;
    const float* row = g_qkv + (size_t)s * HID3;
    for (int idx = threadIdx.x; idx < HID; idx += blockDim.x) {
        const int h = idx / HD;
        const int d = idx - h * HD;
        const float c  = cosb[s * HD + d];
        const float sn = sinb[s * HD + d];
        const int   pidx = (d < 40) ? idx + 40 : idx - 40;
        const float sgn  = (d < 40) ? -1.f : 1.f;
        const float qv = row[idx];
        const float kv = row[HID + idx];
        const float vv = row[2 * HID + idx];
        const float qp = row[pidx] * sgn;
        const float kp = row[HID + pidx] * sgn;
        const size_t oi = ((size_t)h * SQ + s) * HD + d;
        g_q[oi] = qv * c + qp * sn;
        g_k[oi] = kv * c + kp * sn;
        g_v[oi] = vv;
    }
}

// =============================================================================
// Flash attention fp32: grid (S/64, H), 256 threads.
// Per block: 64 query rows of one head; loop over 49 key tiles of 64.
// Smem (dynamic, 78080 B): Qs[80][64] Ks[80][64] Vs[64][80] Ps[64][65]
// =============================================================================
__global__ __launch_bounds__(256)
void flash_kernel()
{
    extern __shared__ float sm[];
    float* Qs = sm;                    // [80][64] k-major
    float* Ks = Qs + 80 * 64;          // [80][64] k-major
    float* Vs = Ks + 80 * 64;          // [64][80] natural
    float* Ps = Vs + 64 * 80;          // [64][65]

    const int tid = threadIdx.x;
    const int tx = tid & 15;           // 0..15
    const int ty = tid >> 4;           // 0..15
    const int hh = blockIdx.y;
    const int q0 = blockIdx.x * 64;

    const float* qh = g_q + (size_t)hh * SQ * HD;
    const float* kh = g_k + (size_t)hh * SQ * HD;
    const float* vh = g_v + (size_t)hh * SQ * HD;

    const int rloc = tid >> 2;         // 0..63
    const int d0   = (tid & 3) * 20;   // 0,20,40,60

    // load Q tile (transposed into Qs[d][row])
#pragma unroll
    for (int u = 0; u < 5; u++) {
        float4 v4 = *(const float4*)&qh[(size_t)(q0 + rloc) * HD + d0 + 4 * u];
        Qs[(d0 + 4 * u + 0) * 64 + rloc] = v4.x;
        Qs[(d0 + 4 * u + 1) * 64 + rloc] = v4.y;
        Qs[(d0 + 4 * u + 2) * 64 + rloc] = v4.z;
        Qs[(d0 + 4 * u + 3) * 64 + rloc] = v4.w;
    }

    float mcur[4], lcur[4], o[4][5];
#pragma unroll
    for (int i = 0; i < 4; i++) {
        mcur[i] = -INFINITY; lcur[i] = 0.f;
#pragma unroll
        for (int j = 0; j < 5; j++) o[i][j] = 0.f;
    }

    for (int kt = 0; kt < SQ / 64; kt++) {
        const int kb = kt * 64;
        // load K (transposed) and V (natural)
#pragma unroll
        for (int u = 0; u < 5; u++) {
            float4 k4 = *(const float4*)&kh[(size_t)(kb + rloc) * HD + d0 + 4 * u];
            Ks[(d0 + 4 * u + 0) * 64 + rloc] = k4.x;
            Ks[(d0 + 4 * u + 1) * 64 + rloc] = k4.y;
            Ks[(d0 + 4 * u + 2) * 64 + rloc] = k4.z;
            Ks[(d0 + 4 * u + 3) * 64 + rloc] = k4.w;
            float4 v4 = *(const float4*)&vh[(size_t)(kb + rloc) * HD + d0 + 4 * u];
            *(float4*)&Vs[rloc * 80 + d0 + 4 * u] = v4;
        }
        __syncthreads();

        // S = Q @ K^T for 4x4 microtile
        float sacc[4][4];
#pragma unroll
        for (int i = 0; i < 4; i++)
#pragma unroll
            for (int j = 0; j < 4; j++) sacc[i][j] = 0.f;

#pragma unroll 8
        for (int kd = 0; kd < HD; kd++) {
            float4 qa = *(const float4*)&Qs[kd * 64 + 4 * ty];
            float4 kb4 = *(const float4*)&Ks[kd * 64 + 4 * tx];
            float qa_[4] = {qa.x, qa.y, qa.z, qa.w};
            float kb_[4] = {kb4.x, kb4.y, kb4.z, kb4.w};
#pragma unroll
            for (int i = 0; i < 4; i++)
#pragma unroll
                for (int j = 0; j < 4; j++)
                    sacc[i][j] += qa_[i] * kb_[j];
        }

        // online softmax update
#pragma unroll
        for (int i = 0; i < 4; i++) {
            float rm = -INFINITY;
#pragma unroll
            for (int j = 0; j < 4; j++) {
                sacc[i][j] *= SCALE;
                rm = fmaxf(rm, sacc[i][j]);
            }
#pragma unroll
            for (int off = 1; off < 16; off <<= 1)
                rm = fmaxf(rm, __shfl_xor_sync(0xffffffffu, rm, off));
            const float mnew = fmaxf(mcur[i], rm);
            const float alpha = __expf(mcur[i] - mnew);
            float rs = 0.f;
#pragma unroll
            for (int j = 0; j < 4; j++) {
                float p = __expf(sacc[i][j] - mnew);
                Ps[(4 * ty + i) * 65 + 4 * tx + j] = p;
                rs += p;
            }
#pragma unroll
            for (int off = 1; off < 16; off <<= 1)
                rs += __shfl_xor_sync(0xffffffffu, rs, off);
            lcur[i] = lcur[i] * alpha + rs;
            mcur[i] = mnew;
#pragma unroll
            for (int j = 0; j < 5; j++) o[i][j] *= alpha;
        }
        __syncthreads();

        // O += P @ V  (4 rows x 5 cols per thread)
#pragma unroll 4
        for (int kk = 0; kk < 64; kk++) {
            float p0 = Ps[(4 * ty + 0) * 65 + kk];
            float p1 = Ps[(4 * ty + 1) * 65 + kk];
            float p2 = Ps[(4 * ty + 2) * 65 + kk];
            float p3 = Ps[(4 * ty + 3) * 65 + kk];
#pragma unroll
            for (int j = 0; j < 5; j++) {
                float vv = Vs[kk * 80 + 5 * tx + j];
                o[0][j] += p0 * vv;
                o[1][j] += p1 * vv;
                o[2][j] += p2 * vv;
                o[3][j] += p3 * vv;
            }
        }
        __syncthreads();
    }

    // write out: attn[s][h*80+d]
#pragma unroll
    for (int i = 0; i < 4; i++) {
        const float inv_l = 1.f / lcur[i];
        const int row = q0 + 4 * ty + i;
#pragma unroll
        for (int j = 0; j < 5; j++)
            g_attn[(size_t)row * HID + hh * HD + 5 * tx + j] = o[i][j] * inv_l;
    }
}

// =============================================================================
// launch
// =============================================================================
extern "C" void kernel_launch(void* const* d_in, const int* in_sizes, int n_in,
                              void* d_out, int out_size)
{
    const float* hidden  = (const float*)d_in[0];
    const float* x_norm  = (const float*)d_in[1];
    const float* qkv_w   = (const float*)d_in[2];
    const float* qkv_b   = (const float*)d_in[3];
    const float* proj_w  = (const float*)d_in[4];
    const float* proj_b  = (const float*)d_in[5];
    const float* cosb    = (const float*)d_in[6];
    const float* sinb    = (const float*)d_in[7];
    float* out = (float*)d_out;

    float* qkv_buf;  cudaGetSymbolAddress((void**)&qkv_buf,  g_qkv);
    float* attn_buf; cudaGetSymbolAddress((void**)&attn_buf, g_attn);

    // 1. qkv = x_norm @ qkv_w^T + qkv_b
    {
        dim3 grid(HID3 / 128, (SQ + 127) / 128);
        sgemm_nt_kernel<false><<<grid, 256>>>(qkv_buf, x_norm, qkv_w, qkv_b,
                                              nullptr, SQ, HID3, HID);
    }
    // 2. rope + split to [H,S,D]
    rope_split_kernel<<<SQ, 256>>>(cosb, sinb);

    // 3. flash attention
    {
        const int smem = (80 * 64 + 80 * 64 + 64 * 80 + 64 * 65) * 4; // 78080
        cudaFuncSetAttribute(flash_kernel,
                             cudaFuncAttributeMaxDynamicSharedMemorySize, smem);
        dim3 grid(SQ / 64, NH);
        flash_kernel<<<grid, 256, smem>>>();
    }
    // 4. out = hidden + attn @ proj_w^T + proj_b
    {
        dim3 grid(HID / 128, (SQ + 127) / 128);
        sgemm_nt_kernel<true><<<grid, 256>>>(out, attn_buf, proj_w, proj_b,
                                             hidden, SQ, HID, HID);
    }
}

// round 4
// speedup vs baseline: 1.0005x; 1.0005x over previous
#include <cuda_runtime.h>
#include <math.h>

// Problem constants
#define SQ   3136          // sequence length
#define NH   16            // heads
#define HD   80            // head dim
#define HID  1280          // NH*HD
#define HID3 3840          // 3*HID
#define SCALE 0.11180339887498948f  // 1/sqrt(80)

// ---------------- scratch (device globals; no allocs allowed) ----------------
__device__ float g_qkv[(size_t)SQ * HID3];            // 48.2 MB
__device__ float g_q[(size_t)NH * SQ * HD];           // 16 MB
__device__ float g_k[(size_t)NH * SQ * HD];           // 16 MB
__device__ float g_v[(size_t)NH * SQ * HD];           // 16 MB
__device__ float g_attn[(size_t)SQ * HID];            // 16 MB

// =============================================================================
// SGEMM NT:  C[M,N] = A[M,K] @ B[N,K]^T + bias[N]  (+ optional residual[M,N])
// BM=BN=128, BK=8, 256 threads, 8x8 microtile (split 4+4 cutlass-style).
// N, K must be multiples of 128 / 8 (true here); M guarded.
// =============================================================================
template <bool RESID>
__global__ __launch_bounds__(256)
void sgemm_nt_kernel(float* __restrict__ C,
                     const float* __restrict__ A,
                     const float* __restrict__ B,
                     const float* __restrict__ bias,
                     const float* __restrict__ Rz,
                     int M, int N, int K)
{
    __shared__ float As[8][128];
    __shared__ float Bs[8][128];

    const int tid = threadIdx.x;
    const int tx = tid & 15;          // 0..15 (N direction)
    const int ty = tid >> 4;          // 0..15 (M direction)
    const int n0 = blockIdx.x * 128;
    const int m0 = blockIdx.y * 128;

    const int lr = tid >> 1;          // 0..127 row within tile
    const int lc = (tid & 1) * 4;     // 0 or 4 k-offset

    float acc[8][8];
#pragma unroll
    for (int i = 0; i < 8; i++)
#pragma unroll
        for (int j = 0; j < 8; j++) acc[i][j] = 0.f;

    for (int k0 = 0; k0 < K; k0 += 8) {
        float4 a4 = make_float4(0.f, 0.f, 0.f, 0.f);
        const int am = m0 + lr;
        if (am < M) a4 = *(const float4*)&A[(size_t)am * K + k0 + lc];
        float4 b4 = *(const float4*)&B[(size_t)(n0 + lr) * K + k0 + lc];

        __syncthreads();   // previous tile's compute done before overwrite
        As[lc + 0][lr] = a4.x;  As[lc + 1][lr] = a4.y;
        As[lc + 2][lr] = a4.z;  As[lc + 3][lr] = a4.w;
        Bs[lc + 0][lr] = b4.x;  Bs[lc + 1][lr] = b4.y;
        Bs[lc + 2][lr] = b4.z;  Bs[lc + 3][lr] = b4.w;
        __syncthreads();

#pragma unroll
        for (int kk = 0; kk < 8; kk++) {
            float4 a0 = *(const float4*)&As[kk][ty * 4];
            float4 a1 = *(const float4*)&As[kk][64 + ty * 4];
            float4 b0 = *(const float4*)&Bs[kk][tx * 4];
            float4 b1 = *(const float4*)&Bs[kk][64 + tx * 4];
            float ar[8] = {a0.x, a0.y, a0.z, a0.w, a1.x, a1.y, a1.z, a1.w};
            float br[8] = {b0.x, b0.y, b0.z, b0.w, b1.x, b1.y, b1.z, b1.w};
#pragma unroll
            for (int i = 0; i < 8; i++)
#pragma unroll
                for (int j = 0; j < 8; j++)
                    acc[i][j] += ar[i] * br[j];
        }
    }

    // epilogue
#pragma unroll
    for (int ih = 0; ih < 2; ih++) {
#pragma unroll
        for (int ii = 0; ii < 4; ii++) {
            const int m = m0 + ih * 64 + ty * 4 + ii;
            if (m >= M) continue;
            const int i = ih * 4 + ii;
#pragma unroll
            for (int jh = 0; jh < 2; jh++) {
                const int n = n0 + jh * 64 + tx * 4;
                float4 bv = *(const float4*)&bias[n];
                float4 o;
                o.x = acc[i][jh * 4 + 0] + bv.x;
                o.y = acc[i][jh * 4 + 1] + bv.y;
                o.z = acc[i][jh * 4 + 2] + bv.z;
                o.w = acc[i][jh * 4 + 3] + bv.w;
                if (RESID) {
                    float4 rv = *(const float4*)&Rz[(size_t)m * N + n];
                    o.x += rv.x; o.y += rv.y; o.z += rv.z; o.w += rv.w;
                }
                *(float4*)&C[(size_t)m * N + n] = o;
            }
        }
    }
}

// =============================================================================
// RoPE + split qkv -> q/k/v in [H, S, D] layout
// =============================================================================
__global__ void rope_split_kernel(const float* __restrict__ cosb,
                                  const float* __restrict__ sinb)
{
    const int s = blockIdx.x;
    const float* row = g_qkv + (size_t)s * HID3;
    for (int idx = threadIdx.x; idx < HID; idx += blockDim.x) {
        const int h = idx / HD;
        const int d = idx - h * HD;
        const float c  = cosb[s * HD + d];
        const float sn = sinb[s * HD + d];
        const int   pidx = (d < 40) ? idx + 40 : idx - 40;
        const float sgn  = (d < 40) ? -1.f : 1.f;
        const float qv = row[idx];
        const float kv = row[HID + idx];
        const float vv = row[2 * HID + idx];
        const float qp = row[pidx] * sgn;
        const float kp = row[HID + pidx] * sgn;
        const size_t oi = ((size_t)h * SQ + s) * HD + d;
        g_q[oi] = qv * c + qp * sn;
        g_k[oi] = kv * c + kp * sn;
        g_v[oi] = vv;
    }
}

// =============================================================================
// Flash attention fp32: grid (S/64, H), 256 threads.
// Per block: 64 query rows of one head; loop over 49 key tiles of 64.
// Smem (dynamic, 78080 B): Qs[80][64] Ks[80][64] Vs[64][80] Ps[64][65]
// =============================================================================
__global__ __launch_bounds__(256)
void flash_kernel()
{
    extern __shared__ float sm[];
    float* Qs = sm;                    // [80][64] k-major
    float* Ks = Qs + 80 * 64;          // [80][64] k-major
    float* Vs = Ks + 80 * 64;          // [64][80] natural
    float* Ps = Vs + 64 * 80;          // [64][65]

    const int tid = threadIdx.x;
    const int tx = tid & 15;           // 0..15
    const int ty = tid >> 4;           // 0..15
    const int hh = blockIdx.y;
    const int q0 = blockIdx.x * 64;

    const float* qh = g_q + (size_t)hh * SQ * HD;
    const float* kh = g_k + (size_t)hh * SQ * HD;
    const float* vh = g_v + (size_t)hh * SQ * HD;

    const int rloc = tid >> 2;         // 0..63
    const int d0   = (tid & 3) * 20;   // 0,20,40,60

    // load Q tile (transposed into Qs[d][row])
#pragma unroll
    for (int u = 0; u < 5; u++) {
        float4 v4 = *(const float4*)&qh[(size_t)(q0 + rloc) * HD + d0 + 4 * u];
        Qs[(d0 + 4 * u + 0) * 64 + rloc] = v4.x;
        Qs[(d0 + 4 * u + 1) * 64 + rloc] = v4.y;
        Qs[(d0 + 4 * u + 2) * 64 + rloc] = v4.z;
        Qs[(d0 + 4 * u + 3) * 64 + rloc] = v4.w;
    }

    float mcur[4], lcur[4], o[4][5];
#pragma unroll
    for (int i = 0; i < 4; i++) {
        mcur[i] = -INFINITY; lcur[i] = 0.f;
#pragma unroll
        for (int j = 0; j < 5; j++) o[i][j] = 0.f;
    }

    for (int kt = 0; kt < SQ / 64; kt++) {
        const int kb = kt * 64;
        // load K (transposed) and V (natural)
#pragma unroll
        for (int u = 0; u < 5; u++) {
            float4 k4 = *(const float4*)&kh[(size_t)(kb + rloc) * HD + d0 + 4 * u];
            Ks[(d0 + 4 * u + 0) * 64 + rloc] = k4.x;
            Ks[(d0 + 4 * u + 1) * 64 + rloc] = k4.y;
            Ks[(d0 + 4 * u + 2) * 64 + rloc] = k4.z;
            Ks[(d0 + 4 * u + 3) * 64 + rloc] = k4.w;
            float4 v4 = *(const float4*)&vh[(size_t)(kb + rloc) * HD + d0 + 4 * u];
            *(float4*)&Vs[rloc * 80 + d0 + 4 * u] = v4;
        }
        __syncthreads();

        // S = Q @ K^T for 4x4 microtile
        float sacc[4][4];
#pragma unroll
        for (int i = 0; i < 4; i++)
#pragma unroll
            for (int j = 0; j < 4; j++) sacc[i][j] = 0.f;

#pragma unroll 8
        for (int kd = 0; kd < HD; kd++) {
            float4 qa = *(const float4*)&Qs[kd * 64 + 4 * ty];
            float4 kb4 = *(const float4*)&Ks[kd * 64 + 4 * tx];
            float qa_[4] = {qa.x, qa.y, qa.z, qa.w};
            float kb_[4] = {kb4.x, kb4.y, kb4.z, kb4.w};
#pragma unroll
            for (int i = 0; i < 4; i++)
#pragma unroll
                for (int j = 0; j < 4; j++)
                    sacc[i][j] += qa_[i] * kb_[j];
        }

        // online softmax update
#pragma unroll
        for (int i = 0; i < 4; i++) {
            float rm = -INFINITY;
#pragma unroll
            for (int j = 0; j < 4; j++) {
                sacc[i][j] *= SCALE;
                rm = fmaxf(rm, sacc[i][j]);
            }
#pragma unroll
            for (int off = 1; off < 16; off <<= 1)
                rm = fmaxf(rm, __shfl_xor_sync(0xffffffffu, rm, off));
            const float mnew = fmaxf(mcur[i], rm);
            const float alpha = __expf(mcur[i] - mnew);
            float rs = 0.f;
#pragma unroll
            for (int j = 0; j < 4; j++) {
                float p = __expf(sacc[i][j] - mnew);
                Ps[(4 * ty + i) * 65 + 4 * tx + j] = p;
                rs += p;
            }
#pragma unroll
            for (int off = 1; off < 16; off <<= 1)
                rs += __shfl_xor_sync(0xffffffffu, rs, off);
            lcur[i] = lcur[i] * alpha + rs;
            mcur[i] = mnew;
#pragma unroll
            for (int j = 0; j < 5; j++) o[i][j] *= alpha;
        }
        __syncthreads();

        // O += P @ V  (4 rows x 5 cols per thread)
#pragma unroll 4
        for (int kk = 0; kk < 64; kk++) {
            float p0 = Ps[(4 * ty + 0) * 65 + kk];
            float p1 = Ps[(4 * ty + 1) * 65 + kk];
            float p2 = Ps[(4 * ty + 2) * 65 + kk];
            float p3 = Ps[(4 * ty + 3) * 65 + kk];
#pragma unroll
            for (int j = 0; j < 5; j++) {
                float vv = Vs[kk * 80 + 5 * tx + j];
                o[0][j] += p0 * vv;
                o[1][j] += p1 * vv;
                o[2][j] += p2 * vv;
                o[3][j] += p3 * vv;
            }
        }
        __syncthreads();
    }

    // write out: attn[s][h*80+d]
#pragma unroll
    for (int i = 0; i < 4; i++) {
        const float inv_l = 1.f / lcur[i];
        const int row = q0 + 4 * ty + i;
#pragma unroll
        for (int j = 0; j < 5; j++)
            g_attn[(size_t)row * HID + hh * HD + 5 * tx + j] = o[i][j] * inv_l;
    }
}

// =============================================================================
// launch
// =============================================================================
extern "C" void kernel_launch(void* const* d_in, const int* in_sizes, int n_in,
                              void* d_out, int out_size)
{
    const float* hidden  = (const float*)d_in[0];
    const float* x_norm  = (const float*)d_in[1];
    const float* qkv_w   = (const float*)d_in[2];
    const float* qkv_b   = (const float*)d_in[3];
    const float* proj_w  = (const float*)d_in[4];
    const float* proj_b  = (const float*)d_in[5];
    const float* cosb    = (const float*)d_in[6];
    const float* sinb    = (const float*)d_in[7];
    float* out = (float*)d_out;

    float* qkv_buf;  cudaGetSymbolAddress((void**)&qkv_buf,  g_qkv);
    float* attn_buf; cudaGetSymbolAddress((void**)&attn_buf, g_attn);

    // 1. qkv = x_norm @ qkv_w^T + qkv_b
    {
        dim3 grid(HID3 / 128, (SQ + 127) / 128);
        sgemm_nt_kernel<false><<<grid, 256>>>(qkv_buf, x_norm, qkv_w, qkv_b,
                                              nullptr, SQ, HID3, HID);
    }
    // 2. rope + split to [H,S,D]
    rope_split_kernel<<<SQ, 256>>>(cosb, sinb);

    // 3. flash attention
    {
        const int smem = (80 * 64 + 80 * 64 + 64 * 80 + 64 * 65) * 4; // 78080
        cudaFuncSetAttribute(flash_kernel,
                             cudaFuncAttributeMaxDynamicSharedMemorySize, smem);
        dim3 grid(SQ / 64, NH);
        flash_kernel<<<grid, 256, smem>>>();
    }
    // 4. out = hidden + attn @ proj_w^T + proj_b
    {
        dim3 grid(HID / 128, (SQ + 127) / 128);
        sgemm_nt_kernel<true><<<grid, 256>>>(out, attn_buf, proj_w, proj_b,
                                             hidden, SQ, HID, HID);
    }
}